// round 4
// baseline (speedup 1.0000x reference)
#include <cuda_runtime.h>
#include <math.h>

#define HID  256
#define ROWS 16
#define NCTA 1024

// flattened float32 output layout:
//   h_next   [0, 4194304)
//   G_struct [4194304, 4194313)
//   G_node   [4194313, 41943049)   (row stride 9*256 = 2304)
//   margins  [41943049, 41943055)
#define O_GS 4194304u
#define O_GN 4194313u
#define O_MG 41943049u

static __device__ float g_u[1024];          // u[k][h] = sum_d L[k][h][d]*Ws[d]
static __device__ float g_v[1024];          // v[k][h] = sum_d R[k][h][d]*Ws[d]
static __device__ float g_cb[4];            // b[k] . Ws
static __device__ float g_SWs;              // sum Ws
static __device__ float g_part[24 * NCTA];  // per-CTA score partial sums

// ---------------------------------------------------------------------------
__global__ void prep_kernel(const float* __restrict__ L, const float* __restrict__ R,
                            const float* __restrict__ bb, const float* __restrict__ Ws) {
    int i = blockIdx.x * blockDim.x + threadIdx.x;
    if (i < 1024) {
        const float* row = L + (size_t)i * HID;
        float s = 0.f;
        for (int t = 0; t < HID; ++t) s += row[t] * Ws[t];
        g_u[i] = s;
    } else if (i < 2048) {
        const float* row = R + (size_t)(i - 1024) * HID;
        float s = 0.f;
        for (int t = 0; t < HID; ++t) s += row[t] * Ws[t];
        g_v[i - 1024] = s;
    } else if (i < 2052) {
        const float* row = bb + (size_t)(i - 2048) * HID;
        float s = 0.f;
        for (int t = 0; t < HID; ++t) s += row[t] * Ws[t];
        g_cb[i - 2048] = s;
    } else if (i == 2052) {
        float s = 0.f;
        for (int t = 0; t < HID; ++t) s += Ws[t];
        g_SWs = s;
    }
}

// ---------------------------------------------------------------------------
// per-row softmax over k=4 + deterministic per-CTA score sums
// caller must have score_s populated and a __syncthreads() before calling.
__device__ __forceinline__ void softmax_gpart(const float* score_s, float* w_s, int mix) {
    int t = threadIdx.x;
    if (t < 16) {
        float s0 = score_s[t*4+0], s1 = score_s[t*4+1];
        float s2 = score_s[t*4+2], s3 = score_s[t*4+3];
        float m = fmaxf(fmaxf(s0, s1), fmaxf(s2, s3));
        float e0 = expf(s0 - m), e1 = expf(s1 - m);
        float e2 = expf(s2 - m), e3 = expf(s3 - m);
        float inv = 1.f / (e0 + e1 + e2 + e3);
        w_s[t*4+0] = e0 * inv; w_s[t*4+1] = e1 * inv;
        w_s[t*4+2] = e2 * inv; w_s[t*4+3] = e3 * inv;
    } else if (t < 20) {
        int k = t - 16;
        float s = 0.f;
        #pragma unroll
        for (int r = 0; r < ROWS; ++r) s += score_s[r*4+k];
        g_part[(mix*4 + k) * NCTA + blockIdx.x] = s;
    }
    __syncthreads();
}

// ---------------------------------------------------------------------------
// additive mixture: cand[b,k,:] = A@L[k] + B@R[k] + b[k]
// scores via precomputed u,v (no cand materialization).
__device__ __forceinline__ void mixture_add(
    const float* __restrict__ AT, const float* __restrict__ BT,
    const float* __restrict__ L, const float* __restrict__ R,
    const float* __restrict__ bb, const float* __restrict__ uvs,
    float* red, float* score_s, float* w_s,
    int mix, int base, float* outT, float* __restrict__ out, int slot, bool hnext)
{
    const int d = threadIdx.x;
    {   // 64 (row,k) pairs x 4 h-quarters
        int p = d >> 2, s4 = d & 3;
        int rr = p >> 2, kk = p & 3;
        const float* uk = uvs + kk * HID;
        const float* vk = uvs + 1024 + kk * HID;
        float s = 0.f;
        int h0 = s4 * 64;
        #pragma unroll 4
        for (int hh = h0; hh < h0 + 64; ++hh)
            s += AT[hh*ROWS + rr] * uk[hh] + BT[hh*ROWS + rr] * vk[hh];
        red[d] = s;
    }
    __syncthreads();
    if (d < 64) {
        float s = g_cb[d & 3];
        #pragma unroll
        for (int q = 0; q < 4; ++q) s += red[d*4 + q];
        score_s[d] = s;
    }
    __syncthreads();
    softmax_gpart(score_s, w_s, mix);

    float outv[ROWS];
    #pragma unroll
    for (int j = 0; j < ROWS; ++j) outv[j] = 0.f;
    #pragma unroll 1
    for (int kk = 0; kk < 4; ++kk) {
        float acc[ROWS];
        #pragma unroll
        for (int j = 0; j < ROWS; ++j) acc[j] = 0.f;
        const float* __restrict__ Lk = L + kk * 65536;
        const float* __restrict__ Rk = R + kk * 65536;
        #pragma unroll 4
        for (int hh = 0; hh < HID; ++hh) {
            float lw = Lk[(hh << 8) + d];
            float rw = Rk[(hh << 8) + d];
            const float4* ap = (const float4*)(AT + hh * ROWS);
            const float4* bp = (const float4*)(BT + hh * ROWS);
            #pragma unroll
            for (int q = 0; q < 4; ++q) {
                float4 a = ap[q], b4 = bp[q];
                acc[q*4+0] += a.x * lw + b4.x * rw;
                acc[q*4+1] += a.y * lw + b4.y * rw;
                acc[q*4+2] += a.z * lw + b4.z * rw;
                acc[q*4+3] += a.w * lw + b4.w * rw;
            }
        }
        float bk = bb[kk * HID + d];
        #pragma unroll
        for (int j = 0; j < ROWS; ++j) outv[j] += w_s[j*4 + kk] * (acc[j] + bk);
    }
    __syncthreads();   // all reads of AT/BT done before (possibly aliased) outT write
    #pragma unroll
    for (int j = 0; j < ROWS; ++j) {
        if (outT) outT[d*ROWS + j] = outv[j];
        size_t ro = (size_t)O_GN + (size_t)(base + j) * 2304 + (size_t)slot * HID + d;
        out[ro] = outv[j];
        if (hnext) out[(size_t)(base + j) * HID + d] = outv[j];
    }
    __syncthreads();
}

// ---------------------------------------------------------------------------
// omz mixture: cand = 1 - (z1@R[k] + b[k]); score = SWs - (z1 . v[k] + cb[k])
__device__ __forceinline__ void mixture_omz(
    const float* __restrict__ AT,
    const float* __restrict__ R, const float* __restrict__ bb,
    const float* __restrict__ uvs, float* red, float* score_s, float* w_s,
    int mix, int base, float* outT, float* __restrict__ out, int slot)
{
    const int d = threadIdx.x;
    {
        int p = d >> 2, s4 = d & 3;
        int rr = p >> 2, kk = p & 3;
        const float* vk = uvs + 1024 + kk * HID;
        float s = 0.f;
        int h0 = s4 * 64;
        #pragma unroll 4
        for (int hh = h0; hh < h0 + 64; ++hh)
            s += AT[hh*ROWS + rr] * vk[hh];
        red[d] = s;
    }
    __syncthreads();
    if (d < 64) {
        float s = 0.f;
        #pragma unroll
        for (int q = 0; q < 4; ++q) s += red[d*4 + q];
        score_s[d] = g_SWs - (s + g_cb[d & 3]);
    }
    __syncthreads();
    softmax_gpart(score_s, w_s, mix);

    float outv[ROWS];
    #pragma unroll
    for (int j = 0; j < ROWS; ++j) outv[j] = 0.f;
    #pragma unroll 1
    for (int kk = 0; kk < 4; ++kk) {
        float acc[ROWS];
        #pragma unroll
        for (int j = 0; j < ROWS; ++j) acc[j] = 0.f;
        const float* __restrict__ Rk = R + kk * 65536;
        #pragma unroll 4
        for (int hh = 0; hh < HID; ++hh) {
            float rw = Rk[(hh << 8) + d];
            const float4* ap = (const float4*)(AT + hh * ROWS);
            #pragma unroll
            for (int q = 0; q < 4; ++q) {
                float4 a = ap[q];
                acc[q*4+0] += a.x * rw;
                acc[q*4+1] += a.y * rw;
                acc[q*4+2] += a.z * rw;
                acc[q*4+3] += a.w * rw;
            }
        }
        float bk = bb[kk * HID + d];
        #pragma unroll
        for (int j = 0; j < ROWS; ++j) outv[j] += w_s[j*4 + kk] * (acc[j] + bk);
    }
    __syncthreads();
    #pragma unroll
    for (int j = 0; j < ROWS; ++j) {
        float val = 1.f - outv[j];
        if (outT) outT[d*ROWS + j] = val;
        size_t ro = (size_t)O_GN + (size_t)(base + j) * 2304 + (size_t)slot * HID + d;
        out[ro] = val;
    }
    __syncthreads();
}

// ---------------------------------------------------------------------------
// multiplicative mixture: cand = (A@L[k]) * (B@R[k]) + b[k]; cand kept in regs.
__device__ __forceinline__ void mixture_mul(
    const float* __restrict__ AT, const float* __restrict__ BT,
    const float* __restrict__ L, const float* __restrict__ R,
    const float* __restrict__ bb, const float* __restrict__ Ws,
    float* red, float* score_s, float* w_s,
    int mix, int base, float* outT, float* __restrict__ out, int slot)
{
    const int d = threadIdx.x;
    const float ws = Ws[d];
    float cand[4][ROWS];
    #pragma unroll
    for (int kk = 0; kk < 4; ++kk) {
        float aA[ROWS], aB[ROWS];
        #pragma unroll
        for (int j = 0; j < ROWS; ++j) { aA[j] = 0.f; aB[j] = 0.f; }
        const float* __restrict__ Lk = L + kk * 65536;
        const float* __restrict__ Rk = R + kk * 65536;
        #pragma unroll 4
        for (int hh = 0; hh < HID; ++hh) {
            float lw = Lk[(hh << 8) + d];
            float rw = Rk[(hh << 8) + d];
            const float4* ap = (const float4*)(AT + hh * ROWS);
            const float4* bp = (const float4*)(BT + hh * ROWS);
            #pragma unroll
            for (int q = 0; q < 4; ++q) {
                float4 a = ap[q], b4 = bp[q];
                aA[q*4+0] += a.x * lw; aA[q*4+1] += a.y * lw;
                aA[q*4+2] += a.z * lw; aA[q*4+3] += a.w * lw;
                aB[q*4+0] += b4.x * rw; aB[q*4+1] += b4.y * rw;
                aB[q*4+2] += b4.z * rw; aB[q*4+3] += b4.w * rw;
            }
        }
        float bk = bb[kk * HID + d];
        #pragma unroll
        for (int j = 0; j < ROWS; ++j) cand[kk][j] = aA[j] * aB[j] + bk;
    }
    // scores: block reduction over d per (row, k)
    #pragma unroll
    for (int kk = 0; kk < 4; ++kk) {
        #pragma unroll
        for (int j = 0; j < ROWS; ++j) red[j*HID + d] = cand[kk][j] * ws;
        __syncthreads();
        int w = d >> 5, lane = d & 31;
        {
            int jj = w;
            float s = 0.f;
            #pragma unroll
            for (int i = 0; i < 8; ++i) s += red[jj*HID + lane + 32*i];
            #pragma unroll
            for (int off = 16; off; off >>= 1) s += __shfl_down_sync(0xffffffffu, s, off);
            if (lane == 0) score_s[jj*4 + kk] = s;
        }
        {
            int jj = w + 8;
            float s = 0.f;
            #pragma unroll
            for (int i = 0; i < 8; ++i) s += red[jj*HID + lane + 32*i];
            #pragma unroll
            for (int off = 16; off; off >>= 1) s += __shfl_down_sync(0xffffffffu, s, off);
            if (lane == 0) score_s[jj*4 + kk] = s;
        }
        __syncthreads();
    }
    softmax_gpart(score_s, w_s, mix);

    float outv[ROWS];
    #pragma unroll
    for (int j = 0; j < ROWS; ++j) outv[j] = 0.f;
    #pragma unroll
    for (int kk = 0; kk < 4; ++kk) {
        #pragma unroll
        for (int j = 0; j < ROWS; ++j) outv[j] += w_s[j*4 + kk] * cand[kk][j];
    }
    #pragma unroll
    for (int j = 0; j < ROWS; ++j) {
        if (outT) outT[d*ROWS + j] = outv[j];
        size_t ro = (size_t)O_GN + (size_t)(base + j) * 2304 + (size_t)slot * HID + d;
        out[ro] = outv[j];
    }
    __syncthreads();
}

// ---------------------------------------------------------------------------
__global__ void __launch_bounds__(256, 2) fused_kernel(
    const float* __restrict__ x, const float* __restrict__ h,
    const float* __restrict__ L, const float* __restrict__ R,
    const float* __restrict__ bb, const float* __restrict__ Ws,
    float* __restrict__ out)
{
    extern __shared__ float sm[];
    float* S0 = sm;              // x2  -> zh_tilde
    float* S1 = sm + 4096;       // h2
    float* S2 = sm + 8192;       // z1 (== z2)
    float* S3 = sm + 12288;      // r -> rh -> h_tilde
    float* S4 = sm + 16384;      // omz -> z2h
    float* uvs = sm + 20480;     // u[1024] | v[1024]
    float* red = sm + 22528;     // 4096
    float* score_s = sm + 26624; // 64
    float* w_s = sm + 26688;     // 64

    const int d = threadIdx.x;
    const int base = blockIdx.x * ROWS;

    #pragma unroll
    for (int i = 0; i < 4; ++i) {
        uvs[i*256 + d] = g_u[i*256 + d];
        uvs[1024 + i*256 + d] = g_v[i*256 + d];
    }
    #pragma unroll
    for (int j = 0; j < ROWS; ++j) {
        S0[d*ROWS + j] = x[(size_t)(base + j) * HID + d];
        S1[d*ROWS + j] = h[(size_t)(base + j) * HID + d];
    }
    __syncthreads();

    // stage 1: z1 = sigmoid(x@L0 + h@R0 + b0) (slots 0,2), r = sigmoid(x@L1 + h@R1 + b1) (slot 1)
    {
        float az[ROWS], ar[ROWS];
        #pragma unroll
        for (int j = 0; j < ROWS; ++j) { az[j] = 0.f; ar[j] = 0.f; }
        const float* __restrict__ L0 = L;
        const float* __restrict__ R0 = R;
        const float* __restrict__ L1 = L + 65536;
        const float* __restrict__ R1 = R + 65536;
        #pragma unroll 4
        for (int hh = 0; hh < HID; ++hh) {
            float l0 = L0[(hh << 8) + d], r0 = R0[(hh << 8) + d];
            float l1 = L1[(hh << 8) + d], r1 = R1[(hh << 8) + d];
            const float4* xp = (const float4*)(S0 + hh * ROWS);
            const float4* hp = (const float4*)(S1 + hh * ROWS);
            #pragma unroll
            for (int q = 0; q < 4; ++q) {
                float4 a = xp[q], b4 = hp[q];
                az[q*4+0] += a.x * l0 + b4.x * r0;
                az[q*4+1] += a.y * l0 + b4.y * r0;
                az[q*4+2] += a.z * l0 + b4.z * r0;
                az[q*4+3] += a.w * l0 + b4.w * r0;
                ar[q*4+0] += a.x * l1 + b4.x * r1;
                ar[q*4+1] += a.y * l1 + b4.y * r1;
                ar[q*4+2] += a.z * l1 + b4.z * r1;
                ar[q*4+3] += a.w * l1 + b4.w * r1;
            }
        }
        float b0 = bb[d], b1 = bb[HID + d];
        #pragma unroll
        for (int j = 0; j < ROWS; ++j) {
            float z  = 1.f / (1.f + expf(-(az[j] + b0)));
            float rr = 1.f / (1.f + expf(-(ar[j] + b1)));
            size_t ro = (size_t)O_GN + (size_t)(base + j) * 2304 + d;
            out[ro]       = z;   // slot 0: z1
            out[ro + 256] = rr;  // slot 1: r
            out[ro + 512] = z;   // slot 2: z2 == z1
            S2[d*ROWS + j] = z;
            S3[d*ROWS + j] = rr;
        }
    }
    __syncthreads();

    // stage 2: rh = mix(lin(h2, r))          -> S3, slot 3, mix 0
    mixture_add(S1, S3, L, R, bb, uvs, red, score_s, w_s, 0, base, S3, out, 3, false);
    // stage 3: h_tilde = mix(lin(x2, rh))    -> S3, slot 4, mix 1
    mixture_add(S0, S3, L, R, bb, uvs, red, score_s, w_s, 1, base, S3, out, 4, false);
    // stage 4: oneMinusZ1 = mix(1-(z1@R+b))  -> S4, slot 5, mix 2
    mixture_omz(S2, R, bb, uvs, red, score_s, w_s, 2, base, S4, out, 5);
    // stage 5: zh_tilde = mix((ht@L)*(omz@R)+b) -> S0, slot 6, mix 3
    mixture_mul(S3, S4, L, R, bb, Ws, red, score_s, w_s, 3, base, S0, out, 6);
    // stage 6: z2h = mix((h2@L)*(z2@R)+b)    -> S4, slot 7, mix 4
    mixture_mul(S1, S2, L, R, bb, Ws, red, score_s, w_s, 4, base, S4, out, 7);
    // stage 7: h_next = mix(lin(zh, z2h))    -> out only, slot 8 + h_next, mix 5
    mixture_add(S0, S4, L, R, bb, uvs, red, score_s, w_s, 5, base, (float*)0, out, 8, true);
}

// ---------------------------------------------------------------------------
__global__ void finalize_kernel(float* __restrict__ out) {
    __shared__ float s_s[24];
    int t = threadIdx.x, w = t >> 5, lane = t & 31;
    if (w < 24) {
        float s = 0.f;
        #pragma unroll 8
        for (int i = 0; i < 32; ++i) s += g_part[w * NCTA + lane + 32*i];
        #pragma unroll
        for (int off = 16; off; off >>= 1) s += __shfl_down_sync(0xffffffffu, s, off);
        if (lane == 0) s_s[w] = s;
    }
    __syncthreads();
    if (t < 6) {
        float a0 = s_s[t*4+0], a1 = s_s[t*4+1], a2 = s_s[t*4+2], a3 = s_s[t*4+3];
        int idx = 0; float mx = a0;
        if (a1 > mx) { mx = a1; idx = 1; }
        if (a2 > mx) { mx = a2; idx = 2; }
        if (a3 > mx) { mx = a3; idx = 3; }
        float mx2 = -3.402823466e38f;
        if (idx != 0 && a0 > mx2) mx2 = a0;
        if (idx != 1 && a1 > mx2) mx2 = a1;
        if (idx != 2 && a2 > mx2) mx2 = a2;
        if (idx != 3 && a3 > mx2) mx2 = a3;
        out[O_GS + 3 + t] = (float)idx;
        out[O_MG + t] = mx - mx2;
    } else if (t == 6) {
        out[O_GS + 0] = 0.f;
        out[O_GS + 1] = 1.f;
        out[O_GS + 2] = 0.f;
    }
}

// ---------------------------------------------------------------------------
extern "C" void kernel_launch(void* const* d_in, const int* in_sizes, int n_in,
                              void* d_out, int out_size) {
    const float* x  = (const float*)d_in[0];
    const float* h  = (const float*)d_in[1];
    const float* L  = (const float*)d_in[2];
    const float* R  = (const float*)d_in[3];
    const float* bb = (const float*)d_in[4];
    const float* Ws = (const float*)d_in[5];
    float* out = (float*)d_out;

    const int smem_bytes = 26752 * 4;  // 107,008 B -> 2 CTAs/SM
    cudaFuncSetAttribute(fused_kernel, cudaFuncAttributeMaxDynamicSharedMemorySize, smem_bytes);

    prep_kernel<<<9, 256>>>(L, R, bb, Ws);
    fused_kernel<<<NCTA, 256, smem_bytes>>>(x, h, L, R, bb, Ws, out);
    finalize_kernel<<<1, 768>>>(out);
}

// round 5
// speedup vs baseline: 1.1143x; 1.1143x over previous
#include <cuda_runtime.h>
#include <math.h>

#define HID  256
#define ROWS 16
#define NCTA 1024

// flattened float32 output layout:
//   h_next   [0, 4194304)
//   G_struct [4194304, 4194313)
//   G_node   [4194313, 41943049)   (row stride 9*256 = 2304)
//   margins  [41943049, 41943055)
#define O_GS 4194304u
#define O_GN 4194313u
#define O_MG 41943049u

typedef unsigned long long u64t;

// ---- packed f32x2 helpers (sm_103a FFMA2 path: only reachable via PTX) ----
__device__ __forceinline__ u64t f2dup(float a) {
    u64t r; asm("mov.b64 %0,{%1,%1};" : "=l"(r) : "f"(a)); return r;
}
__device__ __forceinline__ u64t fpack(float a, float b) {
    u64t r; asm("mov.b64 %0,{%1,%2};" : "=l"(r) : "f"(a), "f"(b)); return r;
}
__device__ __forceinline__ void funpack(float& a, float& b, u64t x) {
    asm("mov.b64 {%0,%1},%2;" : "=f"(a), "=f"(b) : "l"(x));
}
__device__ __forceinline__ u64t ffma2(u64t a, u64t b, u64t c) {
    u64t d; asm("fma.rn.f32x2 %0,%1,%2,%3;" : "=l"(d) : "l"(a), "l"(b), "l"(c)); return d;
}
__device__ __forceinline__ u64t fmul2(u64t a, u64t b) {
    u64t d; asm("mul.rn.f32x2 %0,%1,%2;" : "=l"(d) : "l"(a), "l"(b)); return d;
}
__device__ __forceinline__ u64t fadd2(u64t a, u64t b) {
    u64t d; asm("add.rn.f32x2 %0,%1,%2;" : "=l"(d) : "l"(a), "l"(b)); return d;
}
__device__ __forceinline__ void lds2(u64t& a, u64t& b, unsigned addr) {
    asm volatile("ld.shared.v2.u64 {%0,%1},[%2];" : "=l"(a), "=l"(b) : "r"(addr));
}
__device__ __forceinline__ unsigned sptr(const float* p) {
    return (unsigned)__cvta_generic_to_shared(p);
}

static __device__ float g_u[1024];          // u[k][h] = sum_d L[k][h][d]*Ws[d]
static __device__ float g_v[1024];          // v[k][h] = sum_d R[k][h][d]*Ws[d]
static __device__ float g_cb[4];            // b[k] . Ws
static __device__ float g_SWs;              // sum Ws
static __device__ float g_part[24 * NCTA];  // per-CTA score partial sums

// ---------------------------------------------------------------------------
__global__ void prep_kernel(const float* __restrict__ L, const float* __restrict__ R,
                            const float* __restrict__ bb, const float* __restrict__ Ws) {
    int gw = (blockIdx.x * blockDim.x + threadIdx.x) >> 5;
    int lane = threadIdx.x & 31;
    if (gw >= 2053) return;
    float s = 0.f;
    if (gw < 2052) {
        const float* row;
        if (gw < 1024)      row = L + (size_t)gw * HID;
        else if (gw < 2048) row = R + (size_t)(gw - 1024) * HID;
        else                row = bb + (size_t)(gw - 2048) * HID;
        #pragma unroll
        for (int i = 0; i < 8; ++i) s += row[lane + 32*i] * Ws[lane + 32*i];
    } else {
        #pragma unroll
        for (int i = 0; i < 8; ++i) s += Ws[lane + 32*i];
    }
    #pragma unroll
    for (int off = 16; off; off >>= 1) s += __shfl_down_sync(0xffffffffu, s, off);
    if (lane == 0) {
        if (gw < 1024)      g_u[gw] = s;
        else if (gw < 2048) g_v[gw - 1024] = s;
        else if (gw < 2052) g_cb[gw - 2048] = s;
        else                g_SWs = s;
    }
}

// ---------------------------------------------------------------------------
// per-row softmax over k=4 + deterministic per-CTA score sums
__device__ __forceinline__ void softmax_gpart(const float* score_s, float* w_s, int mix) {
    int t = threadIdx.x;
    if (t < 16) {
        float s0 = score_s[t*4+0], s1 = score_s[t*4+1];
        float s2 = score_s[t*4+2], s3 = score_s[t*4+3];
        float m = fmaxf(fmaxf(s0, s1), fmaxf(s2, s3));
        float e0 = expf(s0 - m), e1 = expf(s1 - m);
        float e2 = expf(s2 - m), e3 = expf(s3 - m);
        float inv = 1.f / (e0 + e1 + e2 + e3);
        w_s[t*4+0] = e0 * inv; w_s[t*4+1] = e1 * inv;
        w_s[t*4+2] = e2 * inv; w_s[t*4+3] = e3 * inv;
    } else if (t < 20) {
        int k = t - 16;
        float s = 0.f;
        #pragma unroll
        for (int r = 0; r < ROWS; ++r) s += score_s[r*4+k];
        g_part[(mix*4 + k) * NCTA + blockIdx.x] = s;
    }
    __syncthreads();
}

// ---------------------------------------------------------------------------
// additive mixture: cand[b,k,:] = A@L[k] + B@R[k] + b[k]
__device__ __forceinline__ void mixture_add(
    const float* __restrict__ AT, const float* __restrict__ BT,
    const float* __restrict__ L, const float* __restrict__ R,
    const float* __restrict__ bb, const float* __restrict__ uvs,
    float* red, float* score_s, float* w_s,
    int mix, int base, float* outT, float* __restrict__ out, int slot, bool hnext)
{
    const int d = threadIdx.x;
    {   // scores via precomputed u,v: 64 (row,k) pairs x 4 h-quarters
        int p = d >> 2, s4 = d & 3;
        int rr = p >> 2, kk = p & 3;
        const float* uk = uvs + kk * HID;
        const float* vk = uvs + 1024 + kk * HID;
        float s = 0.f;
        int h0 = s4 * 64;
        #pragma unroll 4
        for (int hh = h0; hh < h0 + 64; ++hh)
            s += AT[hh*ROWS + rr] * uk[hh] + BT[hh*ROWS + rr] * vk[hh];
        red[d] = s;
    }
    __syncthreads();
    if (d < 64) {
        float s = g_cb[d & 3];
        #pragma unroll
        for (int q = 0; q < 4; ++q) s += red[d*4 + q];
        score_s[d] = s;
    }
    __syncthreads();
    softmax_gpart(score_s, w_s, mix);

    const unsigned at = sptr(AT), bt = sptr(BT);
    u64t outv2[8];
    #pragma unroll
    for (int p = 0; p < 8; ++p) outv2[p] = 0ull;
    #pragma unroll 1
    for (int kk = 0; kk < 4; ++kk) {
        u64t acc2[8];
        #pragma unroll
        for (int p = 0; p < 8; ++p) acc2[p] = 0ull;
        const float* __restrict__ Lk = L + kk * 65536;
        const float* __restrict__ Rk = R + kk * 65536;
        #pragma unroll 4
        for (int hh = 0; hh < HID; ++hh) {
            u64t lw2 = f2dup(Lk[(hh << 8) + d]);
            u64t rw2 = f2dup(Rk[(hh << 8) + d]);
            unsigned ra = at + (hh << 6), rb = bt + (hh << 6);
            u64t a0,a1,a2,a3,a4,a5,a6,a7, c0,c1,c2,c3,c4,c5,c6,c7;
            lds2(a0,a1, ra);      lds2(a2,a3, ra+16);
            lds2(a4,a5, ra+32);   lds2(a6,a7, ra+48);
            lds2(c0,c1, rb);      lds2(c2,c3, rb+16);
            lds2(c4,c5, rb+32);   lds2(c6,c7, rb+48);
            acc2[0]=ffma2(a0,lw2,acc2[0]); acc2[0]=ffma2(c0,rw2,acc2[0]);
            acc2[1]=ffma2(a1,lw2,acc2[1]); acc2[1]=ffma2(c1,rw2,acc2[1]);
            acc2[2]=ffma2(a2,lw2,acc2[2]); acc2[2]=ffma2(c2,rw2,acc2[2]);
            acc2[3]=ffma2(a3,lw2,acc2[3]); acc2[3]=ffma2(c3,rw2,acc2[3]);
            acc2[4]=ffma2(a4,lw2,acc2[4]); acc2[4]=ffma2(c4,rw2,acc2[4]);
            acc2[5]=ffma2(a5,lw2,acc2[5]); acc2[5]=ffma2(c5,rw2,acc2[5]);
            acc2[6]=ffma2(a6,lw2,acc2[6]); acc2[6]=ffma2(c6,rw2,acc2[6]);
            acc2[7]=ffma2(a7,lw2,acc2[7]); acc2[7]=ffma2(c7,rw2,acc2[7]);
        }
        u64t bk2 = f2dup(bb[kk * HID + d]);
        #pragma unroll
        for (int p = 0; p < 8; ++p) {
            u64t w2 = fpack(w_s[8*p + kk], w_s[8*p + 4 + kk]);
            outv2[p] = ffma2(w2, fadd2(acc2[p], bk2), outv2[p]);
        }
    }
    __syncthreads();   // all reads of AT/BT done before (possibly aliased) outT write
    #pragma unroll
    for (int p = 0; p < 8; ++p) {
        float lo, hi; funpack(lo, hi, outv2[p]);
        if (outT) reinterpret_cast<u64t*>(outT)[d*8 + p] = outv2[p];
        size_t ro = (size_t)O_GN + (size_t)(base + 2*p) * 2304 + (size_t)slot * HID + d;
        out[ro] = lo;
        out[ro + 2304] = hi;
        if (hnext) {
            out[(size_t)(base + 2*p) * HID + d] = lo;
            out[(size_t)(base + 2*p + 1) * HID + d] = hi;
        }
    }
    __syncthreads();
}

// ---------------------------------------------------------------------------
// omz mixture: cand = 1 - (z1@R[k] + b[k]); score = SWs - (z1 . v[k] + cb[k])
__device__ __forceinline__ void mixture_omz(
    const float* __restrict__ AT,
    const float* __restrict__ R, const float* __restrict__ bb,
    const float* __restrict__ uvs, float* red, float* score_s, float* w_s,
    int mix, int base, float* outT, float* __restrict__ out, int slot)
{
    const int d = threadIdx.x;
    {
        int p = d >> 2, s4 = d & 3;
        int rr = p >> 2, kk = p & 3;
        const float* vk = uvs + 1024 + kk * HID;
        float s = 0.f;
        int h0 = s4 * 64;
        #pragma unroll 4
        for (int hh = h0; hh < h0 + 64; ++hh)
            s += AT[hh*ROWS + rr] * vk[hh];
        red[d] = s;
    }
    __syncthreads();
    if (d < 64) {
        float s = 0.f;
        #pragma unroll
        for (int q = 0; q < 4; ++q) s += red[d*4 + q];
        score_s[d] = g_SWs - (s + g_cb[d & 3]);
    }
    __syncthreads();
    softmax_gpart(score_s, w_s, mix);

    const unsigned at = sptr(AT);
    u64t outv2[8];
    #pragma unroll
    for (int p = 0; p < 8; ++p) outv2[p] = 0ull;
    #pragma unroll 1
    for (int kk = 0; kk < 4; ++kk) {
        u64t acc2[8];
        #pragma unroll
        for (int p = 0; p < 8; ++p) acc2[p] = 0ull;
        const float* __restrict__ Rk = R + kk * 65536;
        #pragma unroll 4
        for (int hh = 0; hh < HID; ++hh) {
            u64t rw2 = f2dup(Rk[(hh << 8) + d]);
            unsigned ra = at + (hh << 6);
            u64t a0,a1,a2,a3,a4,a5,a6,a7;
            lds2(a0,a1, ra);      lds2(a2,a3, ra+16);
            lds2(a4,a5, ra+32);   lds2(a6,a7, ra+48);
            acc2[0]=ffma2(a0,rw2,acc2[0]); acc2[1]=ffma2(a1,rw2,acc2[1]);
            acc2[2]=ffma2(a2,rw2,acc2[2]); acc2[3]=ffma2(a3,rw2,acc2[3]);
            acc2[4]=ffma2(a4,rw2,acc2[4]); acc2[5]=ffma2(a5,rw2,acc2[5]);
            acc2[6]=ffma2(a6,rw2,acc2[6]); acc2[7]=ffma2(a7,rw2,acc2[7]);
        }
        u64t bk2 = f2dup(bb[kk * HID + d]);
        #pragma unroll
        for (int p = 0; p < 8; ++p) {
            u64t w2 = fpack(w_s[8*p + kk], w_s[8*p + 4 + kk]);
            outv2[p] = ffma2(w2, fadd2(acc2[p], bk2), outv2[p]);
        }
    }
    __syncthreads();
    const u64t one2 = f2dup(1.f);
    #pragma unroll
    for (int p = 0; p < 8; ++p) {
        u64t val2 = fadd2(one2, fmul2(f2dup(-1.f), outv2[p]));
        float lo, hi; funpack(lo, hi, val2);
        if (outT) reinterpret_cast<u64t*>(outT)[d*8 + p] = val2;
        size_t ro = (size_t)O_GN + (size_t)(base + 2*p) * 2304 + (size_t)slot * HID + d;
        out[ro] = lo;
        out[ro + 2304] = hi;
    }
    __syncthreads();
}

// ---------------------------------------------------------------------------
// multiplicative mixture: cand = (A@L[k]) * (B@R[k]) + b[k]
__device__ __forceinline__ void mixture_mul(
    const float* __restrict__ AT, const float* __restrict__ BT,
    const float* __restrict__ L, const float* __restrict__ R,
    const float* __restrict__ bb, const float* __restrict__ Ws,
    float* red, float* score_s, float* w_s,
    int mix, int base, float* outT, float* __restrict__ out, int slot)
{
    const int d = threadIdx.x;
    const unsigned at = sptr(AT), bt = sptr(BT);
    u64t cand2[4][8];
    #pragma unroll 1
    for (int kk = 0; kk < 4; ++kk) {
        u64t aA2[8], aB2[8];
        #pragma unroll
        for (int p = 0; p < 8; ++p) { aA2[p] = 0ull; aB2[p] = 0ull; }
        const float* __restrict__ Lk = L + kk * 65536;
        const float* __restrict__ Rk = R + kk * 65536;
        #pragma unroll 2
        for (int hh = 0; hh < HID; ++hh) {
            u64t lw2 = f2dup(Lk[(hh << 8) + d]);
            u64t rw2 = f2dup(Rk[(hh << 8) + d]);
            unsigned ra = at + (hh << 6), rb = bt + (hh << 6);
            u64t a0,a1,a2,a3,a4,a5,a6,a7, c0,c1,c2,c3,c4,c5,c6,c7;
            lds2(a0,a1, ra);      lds2(a2,a3, ra+16);
            lds2(a4,a5, ra+32);   lds2(a6,a7, ra+48);
            lds2(c0,c1, rb);      lds2(c2,c3, rb+16);
            lds2(c4,c5, rb+32);   lds2(c6,c7, rb+48);
            aA2[0]=ffma2(a0,lw2,aA2[0]); aB2[0]=ffma2(c0,rw2,aB2[0]);
            aA2[1]=ffma2(a1,lw2,aA2[1]); aB2[1]=ffma2(c1,rw2,aB2[1]);
            aA2[2]=ffma2(a2,lw2,aA2[2]); aB2[2]=ffma2(c2,rw2,aB2[2]);
            aA2[3]=ffma2(a3,lw2,aA2[3]); aB2[3]=ffma2(c3,rw2,aB2[3]);
            aA2[4]=ffma2(a4,lw2,aA2[4]); aB2[4]=ffma2(c4,rw2,aB2[4]);
            aA2[5]=ffma2(a5,lw2,aA2[5]); aB2[5]=ffma2(c5,rw2,aB2[5]);
            aA2[6]=ffma2(a6,lw2,aA2[6]); aB2[6]=ffma2(c6,rw2,aB2[6]);
            aA2[7]=ffma2(a7,lw2,aA2[7]); aB2[7]=ffma2(c7,rw2,aB2[7]);
        }
        u64t bk2 = f2dup(bb[kk * HID + d]);
        #pragma unroll
        for (int p = 0; p < 8; ++p) cand2[kk][p] = ffma2(aA2[p], aB2[p], bk2);
    }
    // scores: packed store to red[pair][d] (u64), then per-row block reduction
    u64t* red2 = reinterpret_cast<u64t*>(red);
    const u64t ws2 = f2dup(Ws[d]);
    const int w = d >> 5, lane = d & 31;
    #pragma unroll 1
    for (int kk = 0; kk < 4; ++kk) {
        #pragma unroll
        for (int p = 0; p < 8; ++p) red2[p*256 + d] = fmul2(cand2[kk][p], ws2);
        __syncthreads();
        #pragma unroll
        for (int half = 0; half < 2; ++half) {
            int jj = w + half*8;
            int pr = jj >> 1, cm = jj & 1;
            float s = 0.f;
            #pragma unroll
            for (int i = 0; i < 8; ++i) s += red[pr*512 + (lane + 32*i)*2 + cm];
            #pragma unroll
            for (int off = 16; off; off >>= 1) s += __shfl_down_sync(0xffffffffu, s, off);
            if (lane == 0) score_s[jj*4 + kk] = s;
        }
        __syncthreads();
    }
    softmax_gpart(score_s, w_s, mix);

    u64t outv2[8];
    #pragma unroll
    for (int p = 0; p < 8; ++p) outv2[p] = 0ull;
    #pragma unroll
    for (int kk = 0; kk < 4; ++kk) {
        #pragma unroll
        for (int p = 0; p < 8; ++p) {
            u64t w2 = fpack(w_s[8*p + kk], w_s[8*p + 4 + kk]);
            outv2[p] = ffma2(w2, cand2[kk][p], outv2[p]);
        }
    }
    #pragma unroll
    for (int p = 0; p < 8; ++p) {
        float lo, hi; funpack(lo, hi, outv2[p]);
        if (outT) reinterpret_cast<u64t*>(outT)[d*8 + p] = outv2[p];
        size_t ro = (size_t)O_GN + (size_t)(base + 2*p) * 2304 + (size_t)slot * HID + d;
        out[ro] = lo;
        out[ro + 2304] = hi;
    }
    __syncthreads();
}

// ---------------------------------------------------------------------------
__global__ void __launch_bounds__(256, 2) fused_kernel(
    const float* __restrict__ x, const float* __restrict__ h,
    const float* __restrict__ L, const float* __restrict__ R,
    const float* __restrict__ bb, const float* __restrict__ Ws,
    float* __restrict__ out)
{
    extern __shared__ float sm[];
    float* S0 = sm;              // x2  -> zh_tilde
    float* S1 = sm + 4096;       // h2
    float* S2 = sm + 8192;       // z1 (== z2)
    float* S3 = sm + 12288;      // r -> rh -> h_tilde
    float* S4 = sm + 16384;      // omz -> z2h
    float* uvs = sm + 20480;     // u[1024] | v[1024]
    float* red = sm + 22528;     // 4096
    float* score_s = sm + 26624; // 64
    float* w_s = sm + 26688;     // 64

    const int d = threadIdx.x;
    const int base = blockIdx.x * ROWS;

    #pragma unroll
    for (int i = 0; i < 4; ++i) {
        uvs[i*256 + d] = g_u[i*256 + d];
        uvs[1024 + i*256 + d] = g_v[i*256 + d];
    }
    #pragma unroll
    for (int j = 0; j < ROWS; ++j) {
        S0[d*ROWS + j] = x[(size_t)(base + j) * HID + d];
        S1[d*ROWS + j] = h[(size_t)(base + j) * HID + d];
    }
    __syncthreads();

    // stage 1: z1 = sigmoid(x@L0 + h@R0 + b0) (slots 0,2), r = sigmoid(x@L1 + h@R1 + b1) (slot 1)
    {
        const unsigned xs = sptr(S0), hs = sptr(S1);
        u64t az2[8], ar2[8];
        #pragma unroll
        for (int p = 0; p < 8; ++p) { az2[p] = 0ull; ar2[p] = 0ull; }
        const float* __restrict__ L0 = L;
        const float* __restrict__ R0 = R;
        const float* __restrict__ L1 = L + 65536;
        const float* __restrict__ R1 = R + 65536;
        #pragma unroll 2
        for (int hh = 0; hh < HID; ++hh) {
            u64t l02 = f2dup(L0[(hh << 8) + d]);
            u64t r02 = f2dup(R0[(hh << 8) + d]);
            u64t l12 = f2dup(L1[(hh << 8) + d]);
            u64t r12 = f2dup(R1[(hh << 8) + d]);
            unsigned ra = xs + (hh << 6), rb = hs + (hh << 6);
            u64t a0,a1,a2,a3,a4,a5,a6,a7, c0,c1,c2,c3,c4,c5,c6,c7;
            lds2(a0,a1, ra);      lds2(a2,a3, ra+16);
            lds2(a4,a5, ra+32);   lds2(a6,a7, ra+48);
            lds2(c0,c1, rb);      lds2(c2,c3, rb+16);
            lds2(c4,c5, rb+32);   lds2(c6,c7, rb+48);
            az2[0]=ffma2(a0,l02,az2[0]); az2[0]=ffma2(c0,r02,az2[0]);
            ar2[0]=ffma2(a0,l12,ar2[0]); ar2[0]=ffma2(c0,r12,ar2[0]);
            az2[1]=ffma2(a1,l02,az2[1]); az2[1]=ffma2(c1,r02,az2[1]);
            ar2[1]=ffma2(a1,l12,ar2[1]); ar2[1]=ffma2(c1,r12,ar2[1]);
            az2[2]=ffma2(a2,l02,az2[2]); az2[2]=ffma2(c2,r02,az2[2]);
            ar2[2]=ffma2(a2,l12,ar2[2]); ar2[2]=ffma2(c2,r12,ar2[2]);
            az2[3]=ffma2(a3,l02,az2[3]); az2[3]=ffma2(c3,r02,az2[3]);
            ar2[3]=ffma2(a3,l12,ar2[3]); ar2[3]=ffma2(c3,r12,ar2[3]);
            az2[4]=ffma2(a4,l02,az2[4]); az2[4]=ffma2(c4,r02,az2[4]);
            ar2[4]=ffma2(a4,l12,ar2[4]); ar2[4]=ffma2(c4,r12,ar2[4]);
            az2[5]=ffma2(a5,l02,az2[5]); az2[5]=ffma2(c5,r02,az2[5]);
            ar2[5]=ffma2(a5,l12,ar2[5]); ar2[5]=ffma2(c5,r12,ar2[5]);
            az2[6]=ffma2(a6,l02,az2[6]); az2[6]=ffma2(c6,r02,az2[6]);
            ar2[6]=ffma2(a6,l12,ar2[6]); ar2[6]=ffma2(c6,r12,ar2[6]);
            az2[7]=ffma2(a7,l02,az2[7]); az2[7]=ffma2(c7,r02,az2[7]);
            ar2[7]=ffma2(a7,l12,ar2[7]); ar2[7]=ffma2(c7,r12,ar2[7]);
        }
        float b0 = bb[d], b1 = bb[HID + d];
        #pragma unroll
        for (int p = 0; p < 8; ++p) {
            float azl, azh, arl, arh;
            funpack(azl, azh, az2[p]);
            funpack(arl, arh, ar2[p]);
            float z0  = 1.f / (1.f + expf(-(azl + b0)));
            float z1v = 1.f / (1.f + expf(-(azh + b0)));
            float r0  = 1.f / (1.f + expf(-(arl + b1)));
            float r1v = 1.f / (1.f + expf(-(arh + b1)));
            size_t ro = (size_t)O_GN + (size_t)(base + 2*p) * 2304 + d;
            out[ro]              = z0;   out[ro + 2304]        = z1v;  // slot 0: z1
            out[ro + 256]        = r0;   out[ro + 2304 + 256]  = r1v;  // slot 1: r
            out[ro + 512]        = z0;   out[ro + 2304 + 512]  = z1v;  // slot 2: z2 == z1
            reinterpret_cast<u64t*>(S2)[d*8 + p] = fpack(z0, z1v);
            reinterpret_cast<u64t*>(S3)[d*8 + p] = fpack(r0, r1v);
        }
    }
    __syncthreads();

    // stage 2: rh = mix(lin(h2, r))             -> S3, slot 3, mix 0
    mixture_add(S1, S3, L, R, bb, uvs, red, score_s, w_s, 0, base, S3, out, 3, false);
    // stage 3: h_tilde = mix(lin(x2, rh))       -> S3, slot 4, mix 1
    mixture_add(S0, S3, L, R, bb, uvs, red, score_s, w_s, 1, base, S3, out, 4, false);
    // stage 4: oneMinusZ1 = mix(1-(z1@R+b))     -> S4, slot 5, mix 2
    mixture_omz(S2, R, bb, uvs, red, score_s, w_s, 2, base, S4, out, 5);
    // stage 5: zh_tilde = mix((ht@L)*(omz@R)+b) -> S0, slot 6, mix 3
    mixture_mul(S3, S4, L, R, bb, Ws, red, score_s, w_s, 3, base, S0, out, 6);
    // stage 6: z2h = mix((h2@L)*(z2@R)+b)       -> S4, slot 7, mix 4
    mixture_mul(S1, S2, L, R, bb, Ws, red, score_s, w_s, 4, base, S4, out, 7);
    // stage 7: h_next = mix(lin(zh, z2h))       -> out only, slot 8 + h_next, mix 5
    mixture_add(S0, S4, L, R, bb, uvs, red, score_s, w_s, 5, base, (float*)0, out, 8, true);
}

// ---------------------------------------------------------------------------
__global__ void finalize_kernel(float* __restrict__ out) {
    __shared__ float s_s[24];
    int t = threadIdx.x, w = t >> 5, lane = t & 31;
    if (w < 24) {
        float s = 0.f;
        #pragma unroll 8
        for (int i = 0; i < 32; ++i) s += g_part[w * NCTA + lane + 32*i];
        #pragma unroll
        for (int off = 16; off; off >>= 1) s += __shfl_down_sync(0xffffffffu, s, off);
        if (lane == 0) s_s[w] = s;
    }
    __syncthreads();
    if (t < 6) {
        float a0 = s_s[t*4+0], a1 = s_s[t*4+1], a2 = s_s[t*4+2], a3 = s_s[t*4+3];
        int idx = 0; float mx = a0;
        if (a1 > mx) { mx = a1; idx = 1; }
        if (a2 > mx) { mx = a2; idx = 2; }
        if (a3 > mx) { mx = a3; idx = 3; }
        float mx2 = -3.402823466e38f;
        if (idx != 0 && a0 > mx2) mx2 = a0;
        if (idx != 1 && a1 > mx2) mx2 = a1;
        if (idx != 2 && a2 > mx2) mx2 = a2;
        if (idx != 3 && a3 > mx2) mx2 = a3;
        out[O_GS + 3 + t] = (float)idx;
        out[O_MG + t] = mx - mx2;
    } else if (t == 6) {
        out[O_GS + 0] = 0.f;
        out[O_GS + 1] = 1.f;
        out[O_GS + 2] = 0.f;
    }
}

// ---------------------------------------------------------------------------
extern "C" void kernel_launch(void* const* d_in, const int* in_sizes, int n_in,
                              void* d_out, int out_size) {
    const float* x  = (const float*)d_in[0];
    const float* h  = (const float*)d_in[1];
    const float* L  = (const float*)d_in[2];
    const float* R  = (const float*)d_in[3];
    const float* bb = (const float*)d_in[4];
    const float* Ws = (const float*)d_in[5];
    float* out = (float*)d_out;

    const int smem_bytes = 26752 * 4;  // 107,008 B -> 2 CTAs/SM
    cudaFuncSetAttribute(fused_kernel, cudaFuncAttributeMaxDynamicSharedMemorySize, smem_bytes);

    prep_kernel<<<257, 256>>>(L, R, bb, Ws);
    fused_kernel<<<NCTA, 256, smem_bytes>>>(x, h, L, R, bb, Ws, out);
    finalize_kernel<<<1, 768>>>(out);
}

// round 6
// speedup vs baseline: 1.4593x; 1.3097x over previous
#include <cuda_runtime.h>
#include <math.h>

#define HID  256
#define ROWS 16
#define NCTA 1024

// flattened float32 output layout:
//   h_next   [0, 4194304)
//   G_struct [4194304, 4194313)
//   G_node   [4194313, 41943049)   (row stride 9*256 = 2304)
//   margins  [41943049, 41943055)
#define O_GS 4194304u
#define O_GN 4194313u
#define O_MG 41943049u

typedef unsigned long long u64t;

// ---- packed f32x2 helpers ----
__device__ __forceinline__ u64t f2dup(float a) {
    u64t r; asm("mov.b64 %0,{%1,%1};" : "=l"(r) : "f"(a)); return r;
}
__device__ __forceinline__ u64t fpack(float a, float b) {
    u64t r; asm("mov.b64 %0,{%1,%2};" : "=l"(r) : "f"(a), "f"(b)); return r;
}
__device__ __forceinline__ void funpack(float& a, float& b, u64t x) {
    asm("mov.b64 {%0,%1},%2;" : "=f"(a), "=f"(b) : "l"(x));
}
__device__ __forceinline__ u64t ffma2(u64t a, u64t b, u64t c) {
    u64t d; asm("fma.rn.f32x2 %0,%1,%2,%3;" : "=l"(d) : "l"(a), "l"(b), "l"(c)); return d;
}
__device__ __forceinline__ u64t fmul2(u64t a, u64t b) {
    u64t d; asm("mul.rn.f32x2 %0,%1,%2;" : "=l"(d) : "l"(a), "l"(b)); return d;
}
__device__ __forceinline__ u64t fadd2(u64t a, u64t b) {
    u64t d; asm("add.rn.f32x2 %0,%1,%2;" : "=l"(d) : "l"(a), "l"(b)); return d;
}
__device__ __forceinline__ void lds2(u64t& a, u64t& b, unsigned addr) {
    asm volatile("ld.shared.v2.u64 {%0,%1},[%2];" : "=l"(a), "=l"(b) : "r"(addr));
}
__device__ __forceinline__ unsigned sptr(const float* p) {
    return (unsigned)__cvta_generic_to_shared(p);
}

static __device__ float g_u[1024];
static __device__ float g_v[1024];
static __device__ float g_cb[4];
static __device__ float g_SWs;
static __device__ float g_part[24 * NCTA];

// ---------------------------------------------------------------------------
__global__ void prep_kernel(const float* __restrict__ L, const float* __restrict__ R,
                            const float* __restrict__ bb, const float* __restrict__ Ws) {
    int gw = (blockIdx.x * blockDim.x + threadIdx.x) >> 5;
    int lane = threadIdx.x & 31;
    if (gw >= 2053) return;
    float s = 0.f;
    if (gw < 2052) {
        const float* row;
        if (gw < 1024)      row = L + (size_t)gw * HID;
        else if (gw < 2048) row = R + (size_t)(gw - 1024) * HID;
        else                row = bb + (size_t)(gw - 2048) * HID;
        #pragma unroll
        for (int i = 0; i < 8; ++i) s += row[lane + 32*i] * Ws[lane + 32*i];
    } else {
        #pragma unroll
        for (int i = 0; i < 8; ++i) s += Ws[lane + 32*i];
    }
    #pragma unroll
    for (int off = 16; off; off >>= 1) s += __shfl_down_sync(0xffffffffu, s, off);
    if (lane == 0) {
        if (gw < 1024)      g_u[gw] = s;
        else if (gw < 2048) g_v[gw - 1024] = s;
        else if (gw < 2052) g_cb[gw - 2048] = s;
        else                g_SWs = s;
    }
}

// ---------------------------------------------------------------------------
__device__ __forceinline__ void softmax_gpart(const float* score_s, float* w_s, int mix) {
    int t = threadIdx.x;
    if (t < 16) {
        float s0 = score_s[t*4+0], s1 = score_s[t*4+1];
        float s2 = score_s[t*4+2], s3 = score_s[t*4+3];
        float m = fmaxf(fmaxf(s0, s1), fmaxf(s2, s3));
        float e0 = expf(s0 - m), e1 = expf(s1 - m);
        float e2 = expf(s2 - m), e3 = expf(s3 - m);
        float inv = 1.f / (e0 + e1 + e2 + e3);
        w_s[t*4+0] = e0 * inv; w_s[t*4+1] = e1 * inv;
        w_s[t*4+2] = e2 * inv; w_s[t*4+3] = e3 * inv;
    } else if (t < 20) {
        int k = t - 16;
        float s = 0.f;
        #pragma unroll
        for (int r = 0; r < ROWS; ++r) s += score_s[r*4+k];
        g_part[(mix*4 + k) * NCTA + blockIdx.x] = s;
    }
    __syncthreads();
}

// ---------------------------------------------------------------------------
// paired dual-input GEMM with software-pipelined weight prefetch:
//   accA += AT@Wl0 + BT@Wr0 ;  accB += AT@Wl1 + BT@Wr1   (packed over 16 rows)
__device__ __forceinline__ void gemm_pair_dual(
    unsigned at, unsigned bt,
    const float* __restrict__ Wl0, const float* __restrict__ Wr0,
    const float* __restrict__ Wl1, const float* __restrict__ Wr1,
    int d, u64t* accA, u64t* accB)
{
    float cl0[4], cr0[4], cl1[4], cr1[4];
    #pragma unroll
    for (int i = 0; i < 4; ++i) {
        cl0[i] = Wl0[(i<<8)+d]; cr0[i] = Wr0[(i<<8)+d];
        cl1[i] = Wl1[(i<<8)+d]; cr1[i] = Wr1[(i<<8)+d];
    }
    #pragma unroll 1
    for (int hh = 0; hh < HID; hh += 4) {
        int nh = (hh + 4) & 255;   // wraps to 0 on last iter (harmless extra loads)
        float nl0[4], nr0[4], nl1[4], nr1[4];
        #pragma unroll
        for (int i = 0; i < 4; ++i) {
            nl0[i] = Wl0[((nh+i)<<8)+d]; nr0[i] = Wr0[((nh+i)<<8)+d];
            nl1[i] = Wl1[((nh+i)<<8)+d]; nr1[i] = Wr1[((nh+i)<<8)+d];
        }
        #pragma unroll
        for (int i = 0; i < 4; ++i) {
            u64t lw0 = f2dup(cl0[i]), rw0 = f2dup(cr0[i]);
            u64t lw1 = f2dup(cl1[i]), rw1 = f2dup(cr1[i]);
            unsigned ra = at + ((hh+i) << 6), rb = bt + ((hh+i) << 6);
            u64t a0,a1,c0,c1;
            #pragma unroll
            for (int g = 0; g < 4; ++g) {
                lds2(a0, a1, ra + g*16);
                lds2(c0, c1, rb + g*16);
                accA[g*2+0] = ffma2(a0, lw0, accA[g*2+0]);
                accA[g*2+0] = ffma2(c0, rw0, accA[g*2+0]);
                accB[g*2+0] = ffma2(a0, lw1, accB[g*2+0]);
                accB[g*2+0] = ffma2(c0, rw1, accB[g*2+0]);
                accA[g*2+1] = ffma2(a1, lw0, accA[g*2+1]);
                accA[g*2+1] = ffma2(c1, rw0, accA[g*2+1]);
                accB[g*2+1] = ffma2(a1, lw1, accB[g*2+1]);
                accB[g*2+1] = ffma2(c1, rw1, accB[g*2+1]);
            }
        }
        #pragma unroll
        for (int i = 0; i < 4; ++i) {
            cl0[i] = nl0[i]; cr0[i] = nr0[i];
            cl1[i] = nl1[i]; cr1[i] = nr1[i];
        }
    }
}

// paired single-input GEMM (omz):  accA += AT@W0 ; accB += AT@W1
__device__ __forceinline__ void gemm_pair_single(
    unsigned at,
    const float* __restrict__ W0, const float* __restrict__ W1,
    int d, u64t* accA, u64t* accB)
{
    float c0w[4], c1w[4];
    #pragma unroll
    for (int i = 0; i < 4; ++i) { c0w[i] = W0[(i<<8)+d]; c1w[i] = W1[(i<<8)+d]; }
    #pragma unroll 1
    for (int hh = 0; hh < HID; hh += 4) {
        int nh = (hh + 4) & 255;
        float n0w[4], n1w[4];
        #pragma unroll
        for (int i = 0; i < 4; ++i) { n0w[i] = W0[((nh+i)<<8)+d]; n1w[i] = W1[((nh+i)<<8)+d]; }
        #pragma unroll
        for (int i = 0; i < 4; ++i) {
            u64t w0 = f2dup(c0w[i]), w1 = f2dup(c1w[i]);
            unsigned ra = at + ((hh+i) << 6);
            u64t a0,a1;
            #pragma unroll
            for (int g = 0; g < 4; ++g) {
                lds2(a0, a1, ra + g*16);
                accA[g*2+0] = ffma2(a0, w0, accA[g*2+0]);
                accB[g*2+0] = ffma2(a0, w1, accB[g*2+0]);
                accA[g*2+1] = ffma2(a1, w0, accA[g*2+1]);
                accB[g*2+1] = ffma2(a1, w1, accB[g*2+1]);
            }
        }
        #pragma unroll
        for (int i = 0; i < 4; ++i) { c0w[i] = n0w[i]; c1w[i] = n1w[i]; }
    }
}

// mul-style GEMM for one kk with prefetch: aA += AT@Wl ; aB += BT@Wr
__device__ __forceinline__ void gemm_mul_kk(
    unsigned at, unsigned bt,
    const float* __restrict__ Wl, const float* __restrict__ Wr,
    int d, u64t* aA, u64t* aB)
{
    float cl[4], cr[4];
    #pragma unroll
    for (int i = 0; i < 4; ++i) { cl[i] = Wl[(i<<8)+d]; cr[i] = Wr[(i<<8)+d]; }
    #pragma unroll 1
    for (int hh = 0; hh < HID; hh += 4) {
        int nh = (hh + 4) & 255;
        float nl[4], nr[4];
        #pragma unroll
        for (int i = 0; i < 4; ++i) { nl[i] = Wl[((nh+i)<<8)+d]; nr[i] = Wr[((nh+i)<<8)+d]; }
        #pragma unroll
        for (int i = 0; i < 4; ++i) {
            u64t lw = f2dup(cl[i]), rw = f2dup(cr[i]);
            unsigned ra = at + ((hh+i) << 6), rb = bt + ((hh+i) << 6);
            u64t a0,a1,c0,c1;
            #pragma unroll
            for (int g = 0; g < 4; ++g) {
                lds2(a0, a1, ra + g*16);
                lds2(c0, c1, rb + g*16);
                aA[g*2+0] = ffma2(a0, lw, aA[g*2+0]);
                aB[g*2+0] = ffma2(c0, rw, aB[g*2+0]);
                aA[g*2+1] = ffma2(a1, lw, aA[g*2+1]);
                aB[g*2+1] = ffma2(c1, rw, aB[g*2+1]);
            }
        }
        #pragma unroll
        for (int i = 0; i < 4; ++i) { cl[i] = nl[i]; cr[i] = nr[i]; }
    }
}

// ---------------------------------------------------------------------------
// additive mixture: cand[b,k,:] = A@L[k] + B@R[k] + b[k]
__device__ __forceinline__ void mixture_add(
    const float* __restrict__ AT, const float* __restrict__ BT,
    const float* __restrict__ L, const float* __restrict__ R,
    const float* __restrict__ bb, const float* __restrict__ uvs,
    float* red, float* score_s, float* w_s,
    int mix, int base, float* outT, float* __restrict__ out, int slot, bool hnext)
{
    const int d = threadIdx.x;
    {   // scores via precomputed u,v
        int p = d >> 2, s4 = d & 3;
        int rr = p >> 2, kk = p & 3;
        const float* uk = uvs + kk * HID;
        const float* vk = uvs + 1024 + kk * HID;
        float s = 0.f;
        int h0 = s4 * 64;
        #pragma unroll 4
        for (int hh = h0; hh < h0 + 64; ++hh)
            s += AT[hh*ROWS + rr] * uk[hh] + BT[hh*ROWS + rr] * vk[hh];
        red[d] = s;
    }
    __syncthreads();
    if (d < 64) {
        float s = g_cb[d & 3];
        #pragma unroll
        for (int q = 0; q < 4; ++q) s += red[d*4 + q];
        score_s[d] = s;
    }
    __syncthreads();
    softmax_gpart(score_s, w_s, mix);

    const unsigned at = sptr(AT), bt = sptr(BT);
    u64t outv2[8];
    #pragma unroll
    for (int p = 0; p < 8; ++p) outv2[p] = 0ull;
    #pragma unroll 1
    for (int kp = 0; kp < 2; ++kp) {
        int k0 = 2*kp, k1 = 2*kp + 1;
        u64t accA[8], accB[8];
        #pragma unroll
        for (int p = 0; p < 8; ++p) { accA[p] = 0ull; accB[p] = 0ull; }
        gemm_pair_dual(at, bt, L + k0*65536, R + k0*65536, L + k1*65536, R + k1*65536,
                       d, accA, accB);
        u64t b0 = f2dup(bb[k0 * HID + d]);
        u64t b1 = f2dup(bb[k1 * HID + d]);
        #pragma unroll
        for (int p = 0; p < 8; ++p) {
            u64t wA = fpack(w_s[8*p + k0], w_s[8*p + 4 + k0]);
            u64t wB = fpack(w_s[8*p + k1], w_s[8*p + 4 + k1]);
            outv2[p] = ffma2(wA, fadd2(accA[p], b0), outv2[p]);
            outv2[p] = ffma2(wB, fadd2(accB[p], b1), outv2[p]);
        }
    }
    __syncthreads();   // all reads of AT/BT done before (possibly aliased) outT write
    #pragma unroll
    for (int p = 0; p < 8; ++p) {
        float lo, hi; funpack(lo, hi, outv2[p]);
        if (outT) reinterpret_cast<u64t*>(outT)[d*8 + p] = outv2[p];
        size_t ro = (size_t)O_GN + (size_t)(base + 2*p) * 2304 + (size_t)slot * HID + d;
        out[ro] = lo;
        out[ro + 2304] = hi;
        if (hnext) {
            out[(size_t)(base + 2*p) * HID + d] = lo;
            out[(size_t)(base + 2*p + 1) * HID + d] = hi;
        }
    }
    __syncthreads();
}

// ---------------------------------------------------------------------------
// omz mixture: cand = 1 - (z1@R[k] + b[k]); score = SWs - (z1 . v[k] + cb[k])
__device__ __forceinline__ void mixture_omz(
    const float* __restrict__ AT,
    const float* __restrict__ R, const float* __restrict__ bb,
    const float* __restrict__ uvs, float* red, float* score_s, float* w_s,
    int mix, int base, float* outT, float* __restrict__ out, int slot)
{
    const int d = threadIdx.x;
    {
        int p = d >> 2, s4 = d & 3;
        int rr = p >> 2, kk = p & 3;
        const float* vk = uvs + 1024 + kk * HID;
        float s = 0.f;
        int h0 = s4 * 64;
        #pragma unroll 4
        for (int hh = h0; hh < h0 + 64; ++hh)
            s += AT[hh*ROWS + rr] * vk[hh];
        red[d] = s;
    }
    __syncthreads();
    if (d < 64) {
        float s = 0.f;
        #pragma unroll
        for (int q = 0; q < 4; ++q) s += red[d*4 + q];
        score_s[d] = g_SWs - (s + g_cb[d & 3]);
    }
    __syncthreads();
    softmax_gpart(score_s, w_s, mix);

    const unsigned at = sptr(AT);
    u64t outv2[8];
    #pragma unroll
    for (int p = 0; p < 8; ++p) outv2[p] = 0ull;
    #pragma unroll 1
    for (int kp = 0; kp < 2; ++kp) {
        int k0 = 2*kp, k1 = 2*kp + 1;
        u64t accA[8], accB[8];
        #pragma unroll
        for (int p = 0; p < 8; ++p) { accA[p] = 0ull; accB[p] = 0ull; }
        gemm_pair_single(at, R + k0*65536, R + k1*65536, d, accA, accB);
        u64t b0 = f2dup(bb[k0 * HID + d]);
        u64t b1 = f2dup(bb[k1 * HID + d]);
        #pragma unroll
        for (int p = 0; p < 8; ++p) {
            u64t wA = fpack(w_s[8*p + k0], w_s[8*p + 4 + k0]);
            u64t wB = fpack(w_s[8*p + k1], w_s[8*p + 4 + k1]);
            outv2[p] = ffma2(wA, fadd2(accA[p], b0), outv2[p]);
            outv2[p] = ffma2(wB, fadd2(accB[p], b1), outv2[p]);
        }
    }
    __syncthreads();
    const u64t one2 = f2dup(1.f);
    #pragma unroll
    for (int p = 0; p < 8; ++p) {
        u64t val2 = fadd2(one2, fmul2(f2dup(-1.f), outv2[p]));
        float lo, hi; funpack(lo, hi, val2);
        if (outT) reinterpret_cast<u64t*>(outT)[d*8 + p] = val2;
        size_t ro = (size_t)O_GN + (size_t)(base + 2*p) * 2304 + (size_t)slot * HID + d;
        out[ro] = lo;
        out[ro + 2304] = hi;
    }
    __syncthreads();
}

// ---------------------------------------------------------------------------
// multiplicative mixture: cand = (A@L[k]) * (B@R[k]) + b[k]
__device__ __forceinline__ void mixture_mul(
    const float* __restrict__ AT, const float* __restrict__ BT,
    const float* __restrict__ L, const float* __restrict__ R,
    const float* __restrict__ bb, const float* __restrict__ Ws,
    float* red, float* score_s, float* w_s,
    int mix, int base, float* outT, float* __restrict__ out, int slot)
{
    const int d = threadIdx.x;
    const unsigned at = sptr(AT), bt = sptr(BT);
    u64t cand2[4][8];
    #pragma unroll 1
    for (int kk = 0; kk < 4; ++kk) {
        u64t aA[8], aB[8];
        #pragma unroll
        for (int p = 0; p < 8; ++p) { aA[p] = 0ull; aB[p] = 0ull; }
        gemm_mul_kk(at, bt, L + kk*65536, R + kk*65536, d, aA, aB);
        u64t bk2 = f2dup(bb[kk * HID + d]);
        #pragma unroll
        for (int p = 0; p < 8; ++p) cand2[kk][p] = ffma2(aA[p], aB[p], bk2);
    }
    // scores: packed store to red, per-row block reduction
    u64t* red2 = reinterpret_cast<u64t*>(red);
    const u64t ws2 = f2dup(Ws[d]);
    const int w = d >> 5, lane = d & 31;
    #pragma unroll 1
    for (int kk = 0; kk < 4; ++kk) {
        #pragma unroll
        for (int p = 0; p < 8; ++p) red2[p*256 + d] = fmul2(cand2[kk][p], ws2);
        __syncthreads();
        #pragma unroll
        for (int half = 0; half < 2; ++half) {
            int jj = w + half*8;
            int pr = jj >> 1, cm = jj & 1;
            float s = 0.f;
            #pragma unroll
            for (int i = 0; i < 8; ++i) s += red[pr*512 + (lane + 32*i)*2 + cm];
            #pragma unroll
            for (int off = 16; off; off >>= 1) s += __shfl_down_sync(0xffffffffu, s, off);
            if (lane == 0) score_s[jj*4 + kk] = s;
        }
        __syncthreads();
    }
    softmax_gpart(score_s, w_s, mix);

    u64t outv2[8];
    #pragma unroll
    for (int p = 0; p < 8; ++p) outv2[p] = 0ull;
    #pragma unroll
    for (int kk = 0; kk < 4; ++kk) {
        #pragma unroll
        for (int p = 0; p < 8; ++p) {
            u64t w2 = fpack(w_s[8*p + kk], w_s[8*p + 4 + kk]);
            outv2[p] = ffma2(w2, cand2[kk][p], outv2[p]);
        }
    }
    #pragma unroll
    for (int p = 0; p < 8; ++p) {
        float lo, hi; funpack(lo, hi, outv2[p]);
        if (outT) reinterpret_cast<u64t*>(outT)[d*8 + p] = outv2[p];
        size_t ro = (size_t)O_GN + (size_t)(base + 2*p) * 2304 + (size_t)slot * HID + d;
        out[ro] = lo;
        out[ro + 2304] = hi;
    }
    __syncthreads();
}

// ---------------------------------------------------------------------------
__global__ void __launch_bounds__(256, 2) fused_kernel(
    const float* __restrict__ x, const float* __restrict__ h,
    const float* __restrict__ L, const float* __restrict__ R,
    const float* __restrict__ bb, const float* __restrict__ Ws,
    float* __restrict__ out)
{
    extern __shared__ float sm[];
    float* S0 = sm;              // x2  -> zh_tilde
    float* S1 = sm + 4096;       // h2
    float* S2 = sm + 8192;       // z1 (== z2)
    float* S3 = sm + 12288;      // r -> rh -> h_tilde
    float* S4 = sm + 16384;      // omz -> z2h
    float* uvs = sm + 20480;     // u[1024] | v[1024]
    float* red = sm + 22528;     // 4096
    float* score_s = sm + 26624; // 64
    float* w_s = sm + 26688;     // 64

    const int d = threadIdx.x;
    const int base = blockIdx.x * ROWS;

    #pragma unroll
    for (int i = 0; i < 4; ++i) {
        uvs[i*256 + d] = g_u[i*256 + d];
        uvs[1024 + i*256 + d] = g_v[i*256 + d];
    }
    #pragma unroll
    for (int j = 0; j < ROWS; ++j) {
        S0[d*ROWS + j] = x[(size_t)(base + j) * HID + d];
        S1[d*ROWS + j] = h[(size_t)(base + j) * HID + d];
    }
    __syncthreads();

    // stage 1: z1 = sigmoid(x@L0 + h@R0 + b0), r = sigmoid(x@L1 + h@R1 + b1)
    {
        const unsigned xs = sptr(S0), hs = sptr(S1);
        u64t az2[8], ar2[8];
        #pragma unroll
        for (int p = 0; p < 8; ++p) { az2[p] = 0ull; ar2[p] = 0ull; }
        gemm_pair_dual(xs, hs, L, R, L + 65536, R + 65536, d, az2, ar2);
        float b0 = bb[d], b1 = bb[HID + d];
        #pragma unroll
        for (int p = 0; p < 8; ++p) {
            float azl, azh, arl, arh;
            funpack(azl, azh, az2[p]);
            funpack(arl, arh, ar2[p]);
            float z0  = 1.f / (1.f + expf(-(azl + b0)));
            float z1v = 1.f / (1.f + expf(-(azh + b0)));
            float r0  = 1.f / (1.f + expf(-(arl + b1)));
            float r1v = 1.f / (1.f + expf(-(arh + b1)));
            size_t ro = (size_t)O_GN + (size_t)(base + 2*p) * 2304 + d;
            out[ro]       = z0;  out[ro + 2304]       = z1v;  // slot 0: z1
            out[ro + 256] = r0;  out[ro + 2304 + 256] = r1v;  // slot 1: r
            out[ro + 512] = z0;  out[ro + 2304 + 512] = z1v;  // slot 2: z2 == z1
            reinterpret_cast<u64t*>(S2)[d*8 + p] = fpack(z0, z1v);
            reinterpret_cast<u64t*>(S3)[d*8 + p] = fpack(r0, r1v);
        }
    }
    __syncthreads();

    // stage 2: rh = mix(lin(h2, r))             -> S3, slot 3, mix 0
    mixture_add(S1, S3, L, R, bb, uvs, red, score_s, w_s, 0, base, S3, out, 3, false);
    // stage 3: h_tilde = mix(lin(x2, rh))       -> S3, slot 4, mix 1
    mixture_add(S0, S3, L, R, bb, uvs, red, score_s, w_s, 1, base, S3, out, 4, false);
    // stage 4: oneMinusZ1 = mix(1-(z1@R+b))     -> S4, slot 5, mix 2
    mixture_omz(S2, R, bb, uvs, red, score_s, w_s, 2, base, S4, out, 5);
    // stage 5: zh_tilde = mix((ht@L)*(omz@R)+b) -> S0, slot 6, mix 3
    mixture_mul(S3, S4, L, R, bb, Ws, red, score_s, w_s, 3, base, S0, out, 6);
    // stage 6: z2h = mix((h2@L)*(z2@R)+b)       -> S4, slot 7, mix 4
    mixture_mul(S1, S2, L, R, bb, Ws, red, score_s, w_s, 4, base, S4, out, 7);
    // stage 7: h_next = mix(lin(zh, z2h))       -> out only, slot 8 + h_next, mix 5
    mixture_add(S0, S4, L, R, bb, uvs, red, score_s, w_s, 5, base, (float*)0, out, 8, true);
}

// ---------------------------------------------------------------------------
__global__ void finalize_kernel(float* __restrict__ out) {
    __shared__ float s_s[24];
    int t = threadIdx.x, w = t >> 5, lane = t & 31;
    if (w < 24) {
        float s = 0.f;
        #pragma unroll 8
        for (int i = 0; i < 32; ++i) s += g_part[w * NCTA + lane + 32*i];
        #pragma unroll
        for (int off = 16; off; off >>= 1) s += __shfl_down_sync(0xffffffffu, s, off);
        if (lane == 0) s_s[w] = s;
    }
    __syncthreads();
    if (t < 6) {
        float a0 = s_s[t*4+0], a1 = s_s[t*4+1], a2 = s_s[t*4+2], a3 = s_s[t*4+3];
        int idx = 0; float mx = a0;
        if (a1 > mx) { mx = a1; idx = 1; }
        if (a2 > mx) { mx = a2; idx = 2; }
        if (a3 > mx) { mx = a3; idx = 3; }
        float mx2 = -3.402823466e38f;
        if (idx != 0 && a0 > mx2) mx2 = a0;
        if (idx != 1 && a1 > mx2) mx2 = a1;
        if (idx != 2 && a2 > mx2) mx2 = a2;
        if (idx != 3 && a3 > mx2) mx2 = a3;
        out[O_GS + 3 + t] = (float)idx;
        out[O_MG + t] = mx - mx2;
    } else if (t == 6) {
        out[O_GS + 0] = 0.f;
        out[O_GS + 1] = 1.f;
        out[O_GS + 2] = 0.f;
    }
}

// ---------------------------------------------------------------------------
extern "C" void kernel_launch(void* const* d_in, const int* in_sizes, int n_in,
                              void* d_out, int out_size) {
    const float* x  = (const float*)d_in[0];
    const float* h  = (const float*)d_in[1];
    const float* L  = (const float*)d_in[2];
    const float* R  = (const float*)d_in[3];
    const float* bb = (const float*)d_in[4];
    const float* Ws = (const float*)d_in[5];
    float* out = (float*)d_out;

    const int smem_bytes = 26752 * 4;  // 107,008 B -> 2 CTAs/SM
    cudaFuncSetAttribute(fused_kernel, cudaFuncAttributeMaxDynamicSharedMemorySize, smem_bytes);

    prep_kernel<<<257, 256>>>(L, R, bb, Ws);
    fused_kernel<<<NCTA, 256, smem_bytes>>>(x, h, L, R, bb, Ws, out);
    finalize_kernel<<<1, 768>>>(out);
}